// round 2
// baseline (speedup 1.0000x reference)
#include <cuda_runtime.h>
#include <cuda_bf16.h>

// ROIPooler: multi-level FPN RoIAlign (torchvision semantics, aligned=True)
// Inputs (metadata order): x2 [2,256,200,304], x3 [2,256,100,152],
//                          x4 [2,256,50,76],  x5 [2,256,25,38], boxes [2,256,4]
// Output: [512, 256, 7, 7] float32
//
// Each box is assigned exactly one level:
//   lvl = clip(floor(4 + log2(sqrt(w*h)/224 + 1e-8)), 2, 5) - 2
// and RoIAligned only at that level (the reference computes all 4 and selects).

#define OUTSZ 7
#define SRATE 2
#define NSAMP (OUTSZ * SRATE)     // 14 sample coords per axis
#define NPTS  (NSAMP * NSAMP)     // 196 sample points
#define C_TOT 256
#define N_PER_B 256
#define NBOX_TOT 512
#define CSPLIT 4
#define C_PER (C_TOT / CSPLIT)    // 64 channels per block
#define THREADS 256

__global__ __launch_bounds__(THREADS)
void roi_pooler_kernel(const float* __restrict__ x2,
                       const float* __restrict__ x3,
                       const float* __restrict__ x4,
                       const float* __restrict__ x5,
                       const float* __restrict__ boxes,
                       float* __restrict__ out)
{
    // Per-axis separable tables (stage 1)
    __shared__ int   s_row0[NSAMP], s_row1[NSAMP];   // y0*W, y1*W (clamped, >=0)
    __shared__ int   s_col0[NSAMP], s_col1[NSAMP];   // x0, x1
    __shared__ float s_fy[NSAMP], s_fx[NSAMP];       // frac, zeroed-weight handled below
    __shared__ float s_wy[NSAMP], s_wx[NSAMP];       // validity as 1.0/0.0

    // Per-sample-point fused tables (stage 2): 4 corner offsets + 4 weights
    __shared__ int   s_off[NPTS][4];
    __shared__ float s_wt [NPTS][4];

    const int n   = blockIdx.x;          // box index 0..511
    const int tid = threadIdx.x;

    // ---- per-box params (all threads redundantly; boxes tiny & L1-resident) --
    const float bx1 = __ldg(boxes + n * 4 + 0);
    const float by1 = __ldg(boxes + n * 4 + 1);
    const float bx2 = __ldg(boxes + n * 4 + 2);
    const float by2 = __ldg(boxes + n * 4 + 3);

    const float size = sqrtf((bx2 - bx1) * (by2 - by1));
    float lf = floorf(4.0f + log2f(size / 224.0f + 1e-8f));
    lf = fminf(fmaxf(lf, 2.0f), 5.0f);
    const int lvl = (int)lf - 2;
    const int b = n / N_PER_B;

    int H, W;
    float scale;
    const float* feat;
    switch (lvl) {
        case 0:  H = 200; W = 304; scale = 0.25f;    feat = x2; break;
        case 1:  H = 100; W = 152; scale = 0.125f;   feat = x3; break;
        case 2:  H = 50;  W = 76;  scale = 0.0625f;  feat = x4; break;
        default: H = 25;  W = 38;  scale = 0.03125f; feat = x5; break;
    }
    const int HW = H * W;
    feat += (size_t)b * C_TOT * HW;

    const float X1 = bx1 * scale - 0.5f;
    const float Y1 = by1 * scale - 0.5f;
    const float bin_w = (bx2 - bx1) * scale / (float)OUTSZ;
    const float bin_h = (by2 - by1) * scale / (float)OUTSZ;

    // ---- stage 1: separable per-axis tables ----
    if (tid < NSAMP) {
        const int p = tid >> 1;
        const int s = tid & 1;
        const float g = (float)p + ((float)s + 0.5f) / (float)SRATE;

        {   // y axis
            const float yc = Y1 + g * bin_h;
            const bool valid = (yc >= -1.0f) && (yc <= (float)H);
            float c = fminf(fmaxf(yc, 0.0f), (float)(H - 1));
            const float c0 = floorf(c);
            const int i0 = (int)c0;
            const int i1 = min(i0 + 1, H - 1);
            s_row0[tid] = i0 * W;
            s_row1[tid] = i1 * W;
            s_fy[tid]   = c - c0;
            s_wy[tid]   = valid ? 1.0f : 0.0f;
        }
        {   // x axis
            const float xc = X1 + g * bin_w;
            const bool valid = (xc >= -1.0f) && (xc <= (float)W);
            float c = fminf(fmaxf(xc, 0.0f), (float)(W - 1));
            const float c0 = floorf(c);
            const int i0 = (int)c0;
            const int i1 = min(i0 + 1, W - 1);
            s_col0[tid] = i0;
            s_col1[tid] = i1;
            s_fx[tid]   = c - c0;
            s_wx[tid]   = valid ? 1.0f : 0.0f;
        }
    }
    __syncthreads();

    // ---- stage 2: fuse into per-sample-point corner offsets + weights ----
    // Point index pt = iy * NSAMP + ix. Weight includes validity and the
    // final 1/(SR*SR) averaging factor.
    for (int pt = tid; pt < NPTS; pt += THREADS) {
        const int iy = pt / NSAMP;
        const int ix = pt - iy * NSAMP;
        const float v   = s_wy[iy] * s_wx[ix] * 0.25f;
        const float fy  = s_fy[iy], ofy = 1.0f - s_fy[iy];
        const float fx  = s_fx[ix], ofx = 1.0f - s_fx[ix];
        const int r0 = s_row0[iy], r1 = s_row1[iy];
        const int c0 = s_col0[ix], c1 = s_col1[ix];
        s_off[pt][0] = r0 + c0;  s_wt[pt][0] = v * ofy * ofx;
        s_off[pt][1] = r0 + c1;  s_wt[pt][1] = v * ofy * fx;
        s_off[pt][2] = r1 + c0;  s_wt[pt][2] = v * fy  * ofx;
        s_off[pt][3] = r1 + c1;  s_wt[pt][3] = v * fy  * fx;
    }
    __syncthreads();

    // ---- stage 3: gather + accumulate for this block's channel slice ----
    const int cbase = blockIdx.y * C_PER;
    const int total = C_PER * (OUTSZ * OUTSZ);      // 64 * 49 = 3136

    for (int idx = tid; idx < total; idx += THREADS) {
        const int cq = idx / 49;
        const int r  = idx - cq * 49;
        const int ph = r / 7;
        const int pw = r - ph * 7;
        const int c  = cbase + cq;

        const float* __restrict__ fc = feat + (size_t)c * HW;
        const int ptbase = (2 * ph) * NSAMP + 2 * pw;

        float acc = 0.0f;
        #pragma unroll
        for (int sy = 0; sy < SRATE; sy++) {
            #pragma unroll
            for (int sx = 0; sx < SRATE; sx++) {
                const int pt = ptbase + sy * NSAMP + sx;
                const int   o0 = s_off[pt][0], o1 = s_off[pt][1];
                const int   o2 = s_off[pt][2], o3 = s_off[pt][3];
                const float w0 = s_wt[pt][0],  w1 = s_wt[pt][1];
                const float w2 = s_wt[pt][2],  w3 = s_wt[pt][3];
                acc = fmaf(__ldg(fc + o0), w0, acc);
                acc = fmaf(__ldg(fc + o1), w1, acc);
                acc = fmaf(__ldg(fc + o2), w2, acc);
                acc = fmaf(__ldg(fc + o3), w3, acc);
            }
        }
        out[(size_t)n * (C_TOT * 49) + (size_t)c * 49 + r] = acc;
    }
}

extern "C" void kernel_launch(void* const* d_in, const int* in_sizes, int n_in,
                              void* d_out, int out_size)
{
    const float* x2    = (const float*)d_in[0];
    const float* x3    = (const float*)d_in[1];
    const float* x4    = (const float*)d_in[2];
    const float* x5    = (const float*)d_in[3];
    const float* boxes = (const float*)d_in[4];
    float* out = (float*)d_out;

    dim3 grid(NBOX_TOT, CSPLIT);
    roi_pooler_kernel<<<grid, THREADS>>>(x2, x3, x4, x5, boxes, out);
}